// round 17
// baseline (speedup 1.0000x reference)
#include <cuda_runtime.h>
#include <stdint.h>

// YOLOv5 post-processing v16 (resubmit; R16 was an infra failure, not a kernel
// result) = v15 (best: 43.5us) + u32 dense key store:
//   index is implicit in dense keyarr32 position; cls bits sit below distinct
//   index bits in the sort key (never affect order) -> recomputed at decode.
//   Scatter reads two anchors per LDS.64.
// One block (1024 threads) per image.

#define NANCH    15120
#define KDET     1000
#define NB       128
#define NT       1024
#define NITER    15          // ceil(15120/1024)
#define FULLM    0xFFFFFFFFu
#define NSLOT    1088
#define MSTRIDE  13
#define MAXPAIR  640
#define CONF_THRES 0.25f
#define IOU_THRES  0.45f
#define MAX_WH     4096.0f
#define GAIN       0.5f
#define PAD_H      12.0f
#define LIM_W      1280.0f
#define LIM_H      720.0f

// Output layout (float32): boxes[128,1000,4] | scores[128,1000] | labels | valid
#define OFF_SCORES (NB * KDET * 4)
#define OFF_LABELS (OFF_SCORES + NB * KDET)
#define OFF_VALID  (OFF_LABELS + NB * KDET)

struct SmemT {
    union {
        unsigned int keyarr32[15168] __attribute__((aligned(8)));  // 60672 B
        struct {                                     // NMS overlay (post-sort)
            float4 gbox[NSLOT];                      // 17408
            float garA[NSLOT];                       // 4352
            unsigned int maskS[NSLOT * MSTRIDE];     // 56576
            unsigned int aliveB[NSLOT];              // 4352
        } n;
    } u;   // union sized by the larger member (overlay, ~82.7 KB)
    unsigned int hist[4096];        // counts -> scatter cursors
    unsigned int binstart[4096];    // descending segment starts
    unsigned long long sortbuf[2048];
    unsigned long long wsum[32];
    unsigned int aliveW[34];
    unsigned short pairOff[36];
    unsigned short pairlist[MAXPAIR];   // (j<<8)|k tasks
    int npairs;
};

__global__ __launch_bounds__(NT, 1)
void yolo_nms_kernel(const float* __restrict__ pred, float* __restrict__ out)
{
    extern __shared__ unsigned char smem_raw[];
    SmemT* sm = (SmemT*)smem_raw;

    const int b = blockIdx.x;
    const int t = threadIdx.x;
    const int lane = t & 31;
    const int w = t >> 5;
    const float4* prow = (const float4*)(pred + (size_t)b * NANCH * 8);

    // ---------------- init ----------------
    #pragma unroll
    for (int j = 0; j < 4; ++j) sm->hist[t + j * NT] = 0u;
    __syncthreads();

    // ------- Phase A: single pass, DENSE u32 conf store + histogram -------
    {
        float4 vc = (t < NANCH) ? __ldg(prow + 2 * t + 1)
                                : make_float4(0.f, 0.f, 0.f, 0.f);
        #pragma unroll
        for (int j = 0; j < NITER; ++j) {
            const int i = t + j * NT;
            const int inx = i + NT;
            float4 vn = make_float4(0.f, 0.f, 0.f, 0.f);
            if (j < NITER - 1 && inx < NANCH) vn = __ldg(prow + 2 * inx + 1);

            if (i < NANCH) {
                const float obj = vc.x;
                float conf = obj * vc.y;
                const float m1 = obj * vc.z;
                const float m2 = obj * vc.w;
                if (m1 > conf) conf = m1;
                if (m2 > conf) conf = m2;
                unsigned cb32 = 0u;
                if (conf > CONF_THRES) {
                    cb32 = __float_as_uint(conf);
                    unsigned d = (cb32 >> 12) - 0x3E800u;
                    if (d > 4095u) d = 4095u;
                    atomicAdd(&sm->hist[d], 1u);
                }
                sm->u.keyarr32[i] = cb32;
            }
            vc = vn;
        }
    }
    __syncthreads();

    // ------- suffix scan: hist -> descending segment starts -------
    const unsigned h0 = sm->hist[4 * t + 0];
    const unsigned h1 = sm->hist[4 * t + 1];
    const unsigned h2 = sm->hist[4 * t + 2];
    const unsigned h3 = sm->hist[4 * t + 3];
    const unsigned st = h0 + h1 + h2 + h3;
    unsigned long long sv = st;
    #pragma unroll
    for (int d = 1; d < 32; d <<= 1) {
        unsigned long long tmp = __shfl_down_sync(FULLM, sv, d);
        if (lane + d < 32) sv += tmp;
    }
    if (lane == 0) sm->wsum[w] = sv;
    __syncthreads();
    if (w == 0) {
        unsigned long long x = sm->wsum[lane];
        unsigned long long own = x;
        #pragma unroll
        for (int d = 1; d < 32; d <<= 1) {
            unsigned long long tmp = __shfl_down_sync(FULLM, x, d);
            if (lane + d < 32) x += tmp;
        }
        sm->wsum[lane] = x - own;   // suffix-exclusive over warps
    }
    __syncthreads();
    {
        const unsigned sufThread = (unsigned)(sm->wsum[w] + (sv - st));
        const unsigned s3 = sufThread;
        const unsigned s2 = s3 + h3;
        const unsigned s1 = s2 + h2;
        const unsigned s0 = s1 + h1;
        sm->hist[4 * t + 0] = s0; sm->binstart[4 * t + 0] = s0;
        sm->hist[4 * t + 1] = s1; sm->binstart[4 * t + 1] = s1;
        sm->hist[4 * t + 2] = s2; sm->binstart[4 * t + 2] = s2;
        sm->hist[4 * t + 3] = s3; sm->binstart[4 * t + 3] = s3;
    }
    sm->sortbuf[t] = 0ull;
    sm->sortbuf[t + NT] = 0ull;
    __syncthreads();

    // ------- counting-sort scatter: 2 anchors per LDS.64, pruned -------
    // key64 = conf<<32 | (0x3FFF-i)<<2  (cls bits omitted: below distinct
    // index bits, provably never affect ordering; recomputed at decode).
    {
        const unsigned long long* keypair =
            (const unsigned long long*)sm->u.keyarr32;
        for (int ip = t; ip < NANCH / 2; ip += NT) {
            const unsigned long long pairv = keypair[ip];
            const unsigned cA = (unsigned)pairv;           // anchor 2*ip
            const unsigned cB = (unsigned)(pairv >> 32);   // anchor 2*ip+1
            if (cA) {
                const unsigned d0 = min((cA >> 12) - 0x3E800u, 4095u);
                if (sm->binstart[d0] < 2048u) {
                    const unsigned pos = atomicAdd(&sm->hist[d0], 1u);
                    if (pos < 2048u)
                        sm->sortbuf[pos] = ((unsigned long long)cA << 32)
                            | (unsigned long long)((0x3FFFu - (unsigned)(2 * ip)) << 2);
                }
            }
            if (cB) {
                const unsigned d1 = min((cB >> 12) - 0x3E800u, 4095u);
                if (sm->binstart[d1] < 2048u) {
                    const unsigned pos = atomicAdd(&sm->hist[d1], 1u);
                    if (pos < 2048u)
                        sm->sortbuf[pos] = ((unsigned long long)cB << 32)
                            | (unsigned long long)((0x3FFFu - (unsigned)(2 * ip + 1)) << 2);
                }
            }
        }
    }
    __syncthreads();

    // ------- per-bin insertion sort (desc) for bins intersecting top-K ----
    #pragma unroll
    for (int e = 0; e < 4; ++e) {
        const int d = t + e * NT;
        const int s = (int)sm->binstart[d];
        if (s < KDET) {
            const int en = min((int)sm->hist[d], 2048);
            for (int i = s + 1; i < en; ++i) {
                const unsigned long long key = sm->sortbuf[i];
                int jj = i - 1;
                while (jj >= s && sm->sortbuf[jj] < key) {
                    sm->sortbuf[jj + 1] = sm->sortbuf[jj];
                    --jj;
                }
                sm->sortbuf[jj + 1] = key;
            }
        }
    }
    __syncthreads();

    // ---------------- decode (cls recomputed, same argmax chain) ----------
    const unsigned long long v = sm->sortbuf[t];
    const float score = __uint_as_float((unsigned)(v >> 32));
    const bool haveDet = (t < KDET) && (score > 0.0f);
    float x1 = 0.f, y1 = 0.f, x2 = 0.f, y2 = 0.f;
    float ox1 = 0.f, oy1 = 0.f, ox2 = 0.f, oy2 = 0.f, ar = 0.f;
    int cls = 0;
    if (haveDet) {
        const unsigned lo = (unsigned)v;
        const int idx = (int)(0x3FFFu - (lo >> 2));
        const float4 v0 = __ldg(prow + 2 * idx);
        const float4 v1 = __ldg(prow + 2 * idx + 1);
        const float obj = v1.x;
        float cf = obj * v1.y; cls = 0;
        const float m1 = obj * v1.z;
        const float m2 = obj * v1.w;
        if (m1 > cf) { cf = m1; cls = 1; }
        if (m2 > cf) { cf = m2; cls = 2; }
        const float cx = v0.x, cy = v0.y, ww = v0.z, hh = v0.w;
        x1 = cx - ww / 2.0f; y1 = cy - hh / 2.0f;
        x2 = cx + ww / 2.0f; y2 = cy + hh / 2.0f;
        const float off = (float)cls * MAX_WH;
        ox1 = x1 + off; oy1 = y1 + off; ox2 = x2 + off; oy2 = y2 + off;
        ar = (ox2 - ox1) * (oy2 - oy1);   // ref: area on OFFSET boxes
    }
    const int pcls = haveDet ? cls : 3;

    // ---------------- class partition (packed shfl scan) ---------------
    const unsigned long long myval = 1ull << (16 * pcls);
    unsigned long long x = myval;
    #pragma unroll
    for (int d = 1; d < 32; d <<= 1) {
        const unsigned long long y = __shfl_up_sync(FULLM, x, d);
        if (lane >= d) x += y;
    }
    __syncthreads();
    if (lane == 31) sm->wsum[w] = x;
    __syncthreads();
    if (w == 0) {
        unsigned long long z = sm->wsum[lane];
        #pragma unroll
        for (int d = 1; d < 32; d <<= 1) {
            const unsigned long long y = __shfl_up_sync(FULLM, z, d);
            if (lane >= d) z += y;
        }
        sm->wsum[lane] = z;
    }
    __syncthreads();
    const unsigned long long basep = (w > 0) ? sm->wsum[w - 1] : 0ull;
    const unsigned long long incl = basep + x;
    const unsigned long long tot  = sm->wsum[31];
    const unsigned long long excl = incl - myval;
    const unsigned c0c = (unsigned)(tot & 0xFFFF);
    const unsigned c1c = (unsigned)((tot >> 16) & 0xFFFF);
    const unsigned c2c = (unsigned)((tot >> 32) & 0xFFFF);
    const unsigned b1p = (c0c + 31u) & ~31u;
    const unsigned b2p = b1p + ((c1c + 31u) & ~31u);
    const unsigned Tpad = b2p + c2c;
    const unsigned baseArr[4] = {0u, b1p, b2p, 0u};
    const unsigned mybase = baseArr[pcls];
    const unsigned myrank = (unsigned)(excl >> (16 * pcls)) & 0xFFFFu;
    const unsigned mypos  = mybase + myrank;    // valid only if haveDet
    const int nsteps = max(max(((int)c0c + 31) >> 5, ((int)c1c + 31) >> 5),
                           ((int)c2c + 31) >> 5);
    const int nchTot = ((int)Tpad + 31) >> 5;

    // ---------------- scatter into NMS arrays + pair-task list ---------
    __syncthreads();
    for (int slot = t; slot < NSLOT; slot += NT) {
        sm->u.n.gbox[slot] = make_float4(0.f, 0.f, 0.f, 0.f);
        sm->u.n.garA[slot] = 0.f;
        sm->u.n.aliveB[slot] = 0u;
    }
    if (t == 0) {
        int off = 0;
        for (int j = 0; j < nchTot; ++j) {
            const int jb = j << 5;
            const int fcj = (jb >= (int)b2p) ? ((int)b2p >> 5)
                          : (jb >= (int)b1p) ? ((int)b1p >> 5) : 0;
            sm->pairOff[j] = (unsigned short)off;
            off += min(j - fcj + 1, MSTRIDE);
        }
        sm->npairs = off;
    }
    __syncthreads();
    if (haveDet) {
        sm->u.n.gbox[mypos] = make_float4(ox1, oy1, ox2, oy2);
        sm->u.n.garA[mypos] = ar;
        sm->u.n.aliveB[mypos] = 1u;
    }
    if (t < nchTot) {
        const int j = t;
        const int jb = j << 5;
        const int fcj = (jb >= (int)b2p) ? ((int)b2p >> 5)
                      : (jb >= (int)b1p) ? ((int)b1p >> 5) : 0;
        const int nj = min(j - fcj + 1, MSTRIDE);
        const int o = (int)sm->pairOff[j];
        for (int k = 0; k < nj; ++k)
            sm->pairlist[o + k] = (unsigned short)((j << 8) | k);
    }
    __syncthreads();

    // ---------------- Phase 1: work-balanced mask computation ----------
    const int npairs = sm->npairs;
    for (int pi = w; pi < npairs; pi += 32) {
        const unsigned e = sm->pairlist[pi];
        const int j = (int)(e >> 8);
        const int k = (int)(e & 255u);
        const int jb = j << 5;
        const int fcj = (jb >= (int)b2p) ? ((int)b2p >> 5)
                      : (jb >= (int)b1p) ? ((int)b1p >> 5) : 0;
        const int qbase = (fcj + k) << 5;
        const int slot = jb + lane;
        const float4 mb = sm->u.n.gbox[slot];
        const float  ma = sm->u.n.garA[slot];
        unsigned mask = 0u;
        if (qbase < jb) {
            #pragma unroll 8
            for (int q = qbase; q < qbase + 32; ++q) {
                const float4 qb = sm->u.n.gbox[q];
                const float lx = fmaxf(qb.x, mb.x);
                const float ly = fmaxf(qb.y, mb.y);
                const float rx = fminf(qb.z, mb.z);
                const float ry = fminf(qb.w, mb.w);
                const float ww = fmaxf(rx - lx, 0.0f);
                const float hh = fmaxf(ry - ly, 0.0f);
                const float inter = ww * hh;
                if (inter > IOU_THRES * (sm->u.n.garA[q] + ma - inter))
                    mask |= 1u << (q - qbase);
            }
        } else {
            for (int q = qbase; q < slot; ++q) {
                const float4 qb = sm->u.n.gbox[q];
                const float lx = fmaxf(qb.x, mb.x);
                const float ly = fmaxf(qb.y, mb.y);
                const float rx = fminf(qb.z, mb.z);
                const float ry = fminf(qb.w, mb.w);
                const float ww = fmaxf(rx - lx, 0.0f);
                const float hh = fmaxf(ry - ly, 0.0f);
                const float inter = ww * hh;
                if (inter > IOU_THRES * (sm->u.n.garA[q] + ma - inter))
                    mask |= 1u << (q - qbase);
            }
        }
        sm->u.n.maskS[slot * MSTRIDE + k] = mask;
    }
    __syncthreads();

    // ---------------- Phase 2: per-class parallel wavefront ------------
    for (int s = 0; s < nsteps; ++s) {
        #pragma unroll
        for (int e = 0; e < 2; ++e) {
            int j = -1;
            if (e == 0) j = w;
            else if (w == 31) j = 32;
            else if (w == 30) j = 33;
            if (j >= 0 && j < nchTot) {
                const int jb = j << 5;
                const int fcj = (jb >= (int)b2p) ? ((int)b2p >> 5)
                              : (jb >= (int)b1p) ? ((int)b1p >> 5) : 0;
                if (j - fcj == s) {
                    const int slot = jb + lane;
                    const unsigned mask = sm->u.n.maskS[slot * MSTRIDE + s];
                    bool aliveL = sm->u.n.aliveB[slot] != 0u;
                    const unsigned anyk = __reduce_or_sync(FULLM, mask);
                    unsigned aliveBits = __ballot_sync(FULLM, aliveL);
                    unsigned todo = anyk & aliveBits;
                    while (todo) {
                        const int q = __ffs(todo) - 1;
                        if (lane > q && ((mask >> q) & 1u)) aliveL = false;
                        aliveBits = __ballot_sync(FULLM, aliveL);
                        todo = anyk & aliveBits & (0xFFFFFFFEu << q);
                    }
                    if (lane == 0) sm->aliveW[j] = aliveBits;
                    sm->u.n.aliveB[slot] = aliveL ? 1u : 0u;
                }
            }
        }
        __syncthreads();
        #pragma unroll
        for (int e = 0; e < 2; ++e) {
            const int slot = t + e * NT;
            if (slot >= (int)Tpad) continue;
            if (!sm->u.n.aliveB[slot]) continue;
            const int fcj = (slot >= (int)b2p) ? ((int)b2p >> 5)
                          : (slot >= (int)b1p) ? ((int)b1p >> 5) : 0;
            const int sp = (slot >> 5) - fcj;
            if (s < sp) {
                if (sm->u.n.maskS[slot * MSTRIDE + s] & sm->aliveW[fcj + s])
                    sm->u.n.aliveB[slot] = 0u;
            }
        }
        __syncthreads();
    }

    // ---------------- scale_coords + outputs ---------------------------
    if (t < KDET) {
        const int kkeep = haveDet ? (int)sm->u.n.aliveB[mypos] : 0;
        const float kf = kkeep ? 1.0f : 0.0f;

        const float fx1 = rintf(fminf(fmaxf((x1 - 0.0f) / GAIN, 0.0f), LIM_W));
        const float fy1 = rintf(fminf(fmaxf((y1 - PAD_H) / GAIN, 0.0f), LIM_H));
        const float fx2 = rintf(fminf(fmaxf((x2 - 0.0f) / GAIN, 0.0f), LIM_W));
        const float fy2 = rintf(fminf(fmaxf((y2 - PAD_H) / GAIN, 0.0f), LIM_H));

        ((float4*)out)[b * KDET + t] = make_float4(fx1 * kf, fy1 * kf, fx2 * kf, fy2 * kf);
        out[OFF_SCORES + b * KDET + t] = score * kf;
        out[OFF_LABELS + b * KDET + t] = (float)(kkeep ? (cls + 1) : 0);
        out[OFF_VALID  + b * KDET + t] = kf;
    }
}

extern "C" void kernel_launch(void* const* d_in, const int* in_sizes, int n_in,
                              void* d_out, int out_size)
{
    (void)in_sizes; (void)n_in; (void)out_size;
    const float* pred = (const float*)d_in[0];
    float* out = (float*)d_out;

    cudaFuncSetAttribute(yolo_nms_kernel,
                         cudaFuncAttributeMaxDynamicSharedMemorySize,
                         (int)sizeof(SmemT));
    yolo_nms_kernel<<<NB, NT, sizeof(SmemT)>>>(pred, out);
}